// round 6
// baseline (speedup 1.0000x reference)
#include <cuda_runtime.h>
#include <cstdint>

#define H_DIM   4096
#define R_DIM   16
#define N_TOK   32768
#define NTHREADS 256
#define KSCALE ((float)(2.0 / 0.95))
#define PDROP  0.05f

// kernel1: 8 warps x 2 tokens = 16 tokens/block
#define K1_TBW  2
#define K1_TB   16
// kernel2: 8 warps x 4 tokens = 32 tokens/block, 128-float h slice
#define K2_TPW  4
#define K2_TB   32
#define K2_HB   128

__device__ float g_mid[N_TOK * R_DIM];        // 2 MB scratch
__device__ float g_bt[8 * R_DIM * H_DIM];     // 2 MB: Bt[e][r][h]

// ---------------------------------------------------------------------------
// Kernel 0: transpose lora_b[e][h][r] -> g_bt[e][r][h]  (~6us)
// ---------------------------------------------------------------------------
__global__ void transpose_b_kernel(const float* __restrict__ lora_b)
{
    const int idx = blockIdx.x * blockDim.x + threadIdx.x;   // 524288
    const int r = idx & 15;
    const int h = (idx >> 4) & 4095;
    const int e = idx >> 16;
    g_bt[((size_t)e * R_DIM + r) * H_DIM + h] = lora_b[idx];
}

// ---------------------------------------------------------------------------
// Kernel 1: mid[g][r] = sum_h dropped(g,h) * A[e][r][h]
// 8 warps x 2 tokens. Lanes stride h (float4). All warps walk the SAME A
// addresses -> L1 dedup; block A L2 traffic = 256KB, 2048 blocks = 512MB.
// acc[2][16] = 32 regs; no min-blocks cap so ptxas never spills.
// ---------------------------------------------------------------------------
__global__ __launch_bounds__(NTHREADS)
void lora_mid_kernel(const float* __restrict__ data,
                     const float* __restrict__ mask,
                     const float* __restrict__ lora_a)
{
    const int tid  = threadIdx.x;
    const int wid  = tid >> 5;
    const int lane = tid & 31;
    const int gw   = blockIdx.x * K1_TB + wid * K1_TBW;
    const int e    = blockIdx.x >> 8;            // 256 blocks per expert
    const float* aBase = lora_a + (size_t)e * (R_DIM * H_DIM);

    float acc[K1_TBW][R_DIM];
#pragma unroll
    for (int t = 0; t < K1_TBW; t++)
#pragma unroll
        for (int r = 0; r < R_DIM; r++) acc[t][r] = 0.f;

#pragma unroll 2
    for (int it = 0; it < H_DIM / (4 * 32); it++) {   // 32 iterations
        const int h4 = (it * 32 + lane) * 4;

        float4 dr[K1_TBW];
#pragma unroll
        for (int t = 0; t < K1_TBW; t++) {
            const size_t off = (size_t)(gw + t) * H_DIM + h4;
            float4 x = __ldcs((const float4*)(data + off));
            float4 m = __ldcs((const float4*)(mask + off));
            dr[t].x = (m.x >= PDROP) ? x.x * KSCALE : 0.f;
            dr[t].y = (m.y >= PDROP) ? x.y * KSCALE : 0.f;
            dr[t].z = (m.z >= PDROP) ? x.z * KSCALE : 0.f;
            dr[t].w = (m.w >= PDROP) ? x.w * KSCALE : 0.f;
        }

#pragma unroll
        for (int r = 0; r < R_DIM; r++) {
            const float4 a4 = *(const float4*)(aBase + r * H_DIM + h4);
#pragma unroll
            for (int t = 0; t < K1_TBW; t++) {
                acc[t][r] += dr[t].x * a4.x + dr[t].y * a4.y
                           + dr[t].z * a4.z + dr[t].w * a4.w;
            }
        }
    }

    // warp-private butterfly reduction over h-lanes
#pragma unroll
    for (int t = 0; t < K1_TBW; t++)
#pragma unroll
        for (int r = 0; r < R_DIM; r++) {
#pragma unroll
            for (int off = 16; off > 0; off >>= 1)
                acc[t][r] += __shfl_xor_sync(0xffffffffu, acc[t][r], off);
        }

    if (lane == 0) {
#pragma unroll
        for (int t = 0; t < K1_TBW; t++) {
            float* mp = g_mid + (size_t)(gw + t) * R_DIM;
            *(float4*)(mp + 0)  = make_float4(acc[t][0],  acc[t][1],  acc[t][2],  acc[t][3]);
            *(float4*)(mp + 4)  = make_float4(acc[t][4],  acc[t][5],  acc[t][6],  acc[t][7]);
            *(float4*)(mp + 8)  = make_float4(acc[t][8],  acc[t][9],  acc[t][10], acc[t][11]);
            *(float4*)(mp + 12) = make_float4(acc[t][12], acc[t][13], acc[t][14], acc[t][15]);
        }
    }
}

// ---------------------------------------------------------------------------
// Kernel 2: out[g][h] = result[g][h] + sum_r mid[g][r] * Bt[e][r][h]
// 8 warps x 4 tokens = 32 tokens/block; all warps share the same 128-float
// h slice (lane-indexed) -> Bt L1-dedups to 8KB/block (256MB L2 total).
// mid via LDS.128 warp-uniform broadcast. ~48 regs, MLP_p1=4.
// grid = (N_TOK/32, H/128)
// ---------------------------------------------------------------------------
__global__ __launch_bounds__(NTHREADS)
void lora_out_kernel(const float* __restrict__ result,
                     float* __restrict__ out)
{
    const int tid  = threadIdx.x;
    const int wid  = tid >> 5;
    const int lane = tid & 31;
    const int g0   = blockIdx.x * K2_TB;
    const int e    = blockIdx.x >> 7;            // 128 blocks per expert
    const int h4   = blockIdx.y * K2_HB + lane * 4;
    const int tok0 = wid * K2_TPW;               // this warp's token offset
    const float* btBase = g_bt + (size_t)e * (R_DIM * H_DIM);

    __shared__ float4 smid4[K2_TB * R_DIM / 4];  // 512 floats = 2KB
    if (tid < 128)
        smid4[tid] = *(const float4*)(g_mid + (size_t)g0 * R_DIM + tid * 4);
    __syncthreads();

    float4 acc[K2_TPW];
#pragma unroll
    for (int t = 0; t < K2_TPW; t++)
        acc[t] = __ldcs((const float4*)(result + (size_t)(g0 + tok0 + t) * H_DIM + h4));

#pragma unroll
    for (int rb = 0; rb < 4; rb++) {
        const float4 b0 = *(const float4*)(btBase + (size_t)(rb * 4 + 0) * H_DIM + h4);
        const float4 b1 = *(const float4*)(btBase + (size_t)(rb * 4 + 1) * H_DIM + h4);
        const float4 b2 = *(const float4*)(btBase + (size_t)(rb * 4 + 2) * H_DIM + h4);
        const float4 b3 = *(const float4*)(btBase + (size_t)(rb * 4 + 3) * H_DIM + h4);
#pragma unroll
        for (int t = 0; t < K2_TPW; t++) {
            const float4 m4 = smid4[(tok0 + t) * 4 + rb];   // warp-uniform bcast
            acc[t].x += m4.x * b0.x + m4.y * b1.x + m4.z * b2.x + m4.w * b3.x;
            acc[t].y += m4.x * b0.y + m4.y * b1.y + m4.z * b2.y + m4.w * b3.y;
            acc[t].z += m4.x * b0.z + m4.y * b1.z + m4.z * b2.z + m4.w * b3.z;
            acc[t].w += m4.x * b0.w + m4.y * b1.w + m4.z * b2.w + m4.w * b3.w;
        }
    }

#pragma unroll
    for (int t = 0; t < K2_TPW; t++)
        __stcs((float4*)(out + (size_t)(g0 + tok0 + t) * H_DIM + h4), acc[t]);
}

// ---------------------------------------------------------------------------
extern "C" void kernel_launch(void* const* d_in, const int* in_sizes, int n_in,
                              void* d_out, int out_size)
{
    const float* result   = (const float*)d_in[0];
    const float* data     = (const float*)d_in[1];
    const float* dropmask = (const float*)d_in[2];
    const float* lora_a   = (const float*)d_in[3];
    const float* lora_b   = (const float*)d_in[4];
    float* out = (float*)d_out;

    transpose_b_kernel<<<(8 * R_DIM * H_DIM) / NTHREADS, NTHREADS>>>(lora_b);
    lora_mid_kernel<<<N_TOK / K1_TB, NTHREADS>>>(data, dropmask, lora_a);

    dim3 grid2(N_TOK / K2_TB, H_DIM / K2_HB);
    lora_out_kernel<<<grid2, NTHREADS>>>(result, out);
}